// round 1
// baseline (speedup 1.0000x reference)
#include <cuda_runtime.h>

#define N_NODES  100000
#define N_EDGES  1600000
#define HID      128
#define N_GRAPHS 64
#define N_CLASSES 10

// ---------------- scratch (device globals; no allocation allowed) ----------------
__device__ float g_bufA[N_NODES * HID];   // hidden state ping
__device__ float g_bufB[N_NODES * HID];   // hidden state pong
__device__ float g_mean[N_NODES * HID];   // aggregated mean features
__device__ float g_meanx[N_NODES];        // layer-1 scalar mean
__device__ int   g_cnt[N_NODES];
__device__ int   g_off[N_NODES + 1];
__device__ int   g_cur[N_NODES];
__device__ int   g_eidx[N_EDGES];         // src ids sorted by dst (CSR)
__device__ float g_pool[N_GRAPHS * HID];
__device__ int   g_pcnt[N_GRAPHS];

// ---------------- zero counters / pool ----------------
__global__ void k_zero() {
    int i = blockIdx.x * blockDim.x + threadIdx.x;
    if (i < N_NODES) g_cnt[i] = 0;
    if (i < N_GRAPHS * HID) g_pool[i] = 0.f;
    if (i < N_GRAPHS) g_pcnt[i] = 0;
}

// ---------------- degree histogram ----------------
__global__ void k_hist(const int* __restrict__ dst) {
    int e = blockIdx.x * blockDim.x + threadIdx.x;
    if (e < N_EDGES) atomicAdd(&g_cnt[dst[e]], 1);
}

// ---------------- single-block exclusive scan over g_cnt -> g_off, g_cur --------
__global__ void k_scan() {
    __shared__ int warpsum[32];
    __shared__ int carry_s;
    const int t = threadIdx.x, lane = t & 31, wid = t >> 5;
    if (t == 0) carry_s = 0;
    __syncthreads();
    for (int base = 0; base < N_NODES; base += 1024) {
        int i = base + t;
        int v = (i < N_NODES) ? g_cnt[i] : 0;
        int x = v;
        #pragma unroll
        for (int o = 1; o < 32; o <<= 1) {
            int y = __shfl_up_sync(0xffffffff, x, o);
            if (lane >= o) x += y;
        }
        if (lane == 31) warpsum[wid] = x;      // inclusive warp total
        __syncthreads();
        if (wid == 0) {
            int w = warpsum[lane];
            int xs = w;
            #pragma unroll
            for (int o = 1; o < 32; o <<= 1) {
                int y = __shfl_up_sync(0xffffffff, xs, o);
                if (lane >= o) xs += y;
            }
            warpsum[lane] = xs - w;            // exclusive warp prefix
        }
        __syncthreads();
        int excl = carry_s + warpsum[wid] + x - v;
        if (i < N_NODES) { g_off[i] = excl; g_cur[i] = excl; }
        __syncthreads();
        if (t == 1023) carry_s += warpsum[31] + x;  // chunk total
        __syncthreads();
    }
    if (t == 0) g_off[N_NODES] = carry_s;
}

// ---------------- scatter edges into CSR slots ----------------
__global__ void k_scatter(const int* __restrict__ src, const int* __restrict__ dst) {
    int e = blockIdx.x * blockDim.x + threadIdx.x;
    if (e < N_EDGES) {
        int pos = atomicAdd(&g_cur[dst[e]], 1);
        g_eidx[pos] = src[e];
    }
}

// ---------------- layer-1 scalar aggregation ----------------
__global__ void k_aggx(const float* __restrict__ x) {
    int i = blockIdx.x * blockDim.x + threadIdx.x;
    if (i >= N_NODES) return;
    int b = g_off[i], e = g_off[i + 1];
    float s = 0.f;
    for (int j = b; j < e; j++) s += __ldg(&x[g_eidx[j]]);
    g_meanx[i] = s / (float)max(e - b, 1);
}

// ---------------- layer 1: h = relu(meanx*W1l + x*W1r + b1) ----------------
__global__ void k_layer1(const float* __restrict__ x,
                         const float* __restrict__ W1l,
                         const float* __restrict__ W1r,
                         const float* __restrict__ b1,
                         float* __restrict__ out) {
    int idx = blockIdx.x * blockDim.x + threadIdx.x;
    if (idx >= N_NODES * HID) return;
    int i = idx >> 7;
    int f = idx & 127;
    float v = g_meanx[i] * __ldg(&W1l[f]) + __ldg(&x[i]) * __ldg(&W1r[f]) + __ldg(&b1[f]);
    out[idx] = fmaxf(v, 0.f);
}

// ---------------- 128-dim mean aggregation: warp per node ----------------
__global__ void k_agg(const float* __restrict__ h, float* __restrict__ outMean) {
    int node = (blockIdx.x * blockDim.x + threadIdx.x) >> 5;
    int lane = threadIdx.x & 31;
    if (node >= N_NODES) return;
    int beg = g_off[node], end = g_off[node + 1];
    float ax = 0.f, ay = 0.f, az = 0.f, aw = 0.f;
    const float4* hv = (const float4*)h;
    for (int e = beg; e < end; e++) {
        int s = __ldg(&g_eidx[e]);
        float4 v = __ldg(&hv[s * 32 + lane]);
        ax += v.x; ay += v.y; az += v.z; aw += v.w;
    }
    float inv = 1.f / (float)max(end - beg, 1);
    float4 o = make_float4(ax * inv, ay * inv, az * inv, aw * inv);
    ((float4*)outMean)[node * 32 + lane] = o;
}

// ---------------- fused SAGE GEMM: out = relu(mean@Wl + h@Wr + b) -------------
// M = N_NODES, K = 256 (mean || h), N = 128.  BM=64, BN=128, BK=16.
// 256 threads, each computes 8 rows x 4 cols.
__global__ __launch_bounds__(256) void k_gemm(const float* __restrict__ Am,
                                              const float* __restrict__ Ah,
                                              const float* __restrict__ Wl,
                                              const float* __restrict__ Wr,
                                              const float* __restrict__ b,
                                              float* __restrict__ out) {
    __shared__ float As[16][64];
    __shared__ float Ws[16][128];
    const int t = threadIdx.x;
    const int tm = t >> 5;            // 0..7  (warp id)
    const int tn = t & 31;            // 0..31
    const int m0 = blockIdx.x * 64;

    float acc[8][4];
    #pragma unroll
    for (int r = 0; r < 8; r++)
        #pragma unroll
        for (int j = 0; j < 4; j++) acc[r][j] = 0.f;

    float bias[4];
    #pragma unroll
    for (int j = 0; j < 4; j++) bias[j] = __ldg(&b[tn * 4 + j]);

    for (int kb = 0; kb < 256; kb += 16) {
        const float* Abase = (kb < 128) ? Am : Ah;
        const float* Wbase = (kb < 128) ? Wl : Wr;
        const int kOff = kb & 127;
        // A tile: 64 rows x 16 k  (one float4 per thread)
        {
            int row = t >> 2;
            int c4  = (t & 3) * 4;
            int gr  = m0 + row;
            float4 v = make_float4(0.f, 0.f, 0.f, 0.f);
            if (gr < N_NODES) v = __ldg((const float4*)&Abase[gr * HID + kOff + c4]);
            As[c4 + 0][row] = v.x; As[c4 + 1][row] = v.y;
            As[c4 + 2][row] = v.z; As[c4 + 3][row] = v.w;
        }
        // W tile: 16 rows x 128 (two float4 per thread)
        #pragma unroll
        for (int i = 0; i < 2; i++) {
            int idx = t + i * 256;     // 0..511
            int kr  = idx >> 5;
            int c4  = (idx & 31) * 4;
            *(float4*)&Ws[kr][c4] = __ldg((const float4*)&Wbase[(kOff + kr) * HID + c4]);
        }
        __syncthreads();
        #pragma unroll
        for (int k = 0; k < 16; k++) {
            float4 w  = *(float4*)&Ws[k][tn * 4];
            float4 a0 = *(float4*)&As[k][tm * 8];
            float4 a1 = *(float4*)&As[k][tm * 8 + 4];
            float a[8] = {a0.x, a0.y, a0.z, a0.w, a1.x, a1.y, a1.z, a1.w};
            float wj[4] = {w.x, w.y, w.z, w.w};
            #pragma unroll
            for (int r = 0; r < 8; r++)
                #pragma unroll
                for (int j = 0; j < 4; j++)
                    acc[r][j] += a[r] * wj[j];
        }
        __syncthreads();
    }
    #pragma unroll
    for (int r = 0; r < 8; r++) {
        int gr = m0 + tm * 8 + r;
        if (gr < N_NODES) {
            float4 o;
            o.x = fmaxf(acc[r][0] + bias[0], 0.f);
            o.y = fmaxf(acc[r][1] + bias[1], 0.f);
            o.z = fmaxf(acc[r][2] + bias[2], 0.f);
            o.w = fmaxf(acc[r][3] + bias[3], 0.f);
            *(float4*)&out[gr * HID + tn * 4] = o;
        }
    }
}

// ---------------- global mean pool (segment accumulate; batch is sorted) -------
__global__ void k_pool(const float* __restrict__ h, const int* __restrict__ batch) {
    const int f = threadIdx.x;          // 128 threads
    const int start = blockIdx.x * 256;
    if (start >= N_NODES) return;
    const int end = min(start + 256, N_NODES);
    float sum = 0.f;
    int cnt = 0;
    int cur = __ldg(&batch[start]);
    for (int i = start; i < end; i++) {
        int gid = __ldg(&batch[i]);
        if (gid != cur) {
            atomicAdd(&g_pool[cur * HID + f], sum);
            if (f == 0) atomicAdd(&g_pcnt[cur], cnt);
            sum = 0.f; cnt = 0; cur = gid;
        }
        sum += h[i * HID + f];
        cnt++;
    }
    atomicAdd(&g_pool[cur * HID + f], sum);
    if (f == 0) atomicAdd(&g_pcnt[cur], cnt);
}

// ---------------- final FC + log_softmax ----------------
__global__ void k_final(const float* __restrict__ Wfc,
                        const float* __restrict__ bfc,
                        float* __restrict__ out) {
    int g = threadIdx.x;
    if (g >= N_GRAPHS) return;
    float inv = 1.f / fmaxf((float)g_pcnt[g], 1.f);
    float logits[N_CLASSES];
    #pragma unroll
    for (int c = 0; c < N_CLASSES; c++) logits[c] = __ldg(&bfc[c]);
    for (int k = 0; k < HID; k++) {
        float p = g_pool[g * HID + k] * inv;
        #pragma unroll
        for (int c = 0; c < N_CLASSES; c++)
            logits[c] += p * __ldg(&Wfc[k * N_CLASSES + c]);
    }
    float mx = logits[0];
    #pragma unroll
    for (int c = 1; c < N_CLASSES; c++) mx = fmaxf(mx, logits[c]);
    float s = 0.f;
    #pragma unroll
    for (int c = 0; c < N_CLASSES; c++) s += expf(logits[c] - mx);
    float lse = logf(s) + mx;
    #pragma unroll
    for (int c = 0; c < N_CLASSES; c++) out[g * N_CLASSES + c] = logits[c] - lse;
}

// ---------------- launch ----------------
extern "C" void kernel_launch(void* const* d_in, const int* in_sizes, int n_in,
                              void* d_out, int out_size) {
    const float* x     = (const float*)d_in[0];
    const int*   eidx  = (const int*)d_in[1];
    const int*   batch = (const int*)d_in[2];
    const float* W1l = (const float*)d_in[3];
    const float* W1r = (const float*)d_in[4];
    const float* b1  = (const float*)d_in[5];
    const float* W2l = (const float*)d_in[6];
    const float* W2r = (const float*)d_in[7];
    const float* b2  = (const float*)d_in[8];
    const float* W3l = (const float*)d_in[9];
    const float* W3r = (const float*)d_in[10];
    const float* b3  = (const float*)d_in[11];
    const float* Wfc = (const float*)d_in[12];
    const float* bfc = (const float*)d_in[13];
    float* out = (float*)d_out;

    const int* src = eidx;
    const int* dst = eidx + N_EDGES;

    float *bufA, *bufB, *meanB;
    cudaGetSymbolAddress((void**)&bufA,  g_bufA);
    cudaGetSymbolAddress((void**)&bufB,  g_bufB);
    cudaGetSymbolAddress((void**)&meanB, g_mean);

    // CSR build
    k_zero<<<(N_NODES + 255) / 256, 256>>>();
    k_hist<<<(N_EDGES + 255) / 256, 256>>>(dst);
    k_scan<<<1, 1024>>>();
    k_scatter<<<(N_EDGES + 255) / 256, 256>>>(src, dst);

    // layer 1 (scalar features)
    k_aggx<<<(N_NODES + 255) / 256, 256>>>(x);
    k_layer1<<<(N_NODES * HID + 255) / 256, 256>>>(x, W1l, W1r, b1, bufA);

    // layer 2
    k_agg<<<(N_NODES * 32 + 255) / 256, 256>>>(bufA, meanB);
    k_gemm<<<(N_NODES + 63) / 64, 256>>>(meanB, bufA, W2l, W2r, b2, bufB);

    // layer 3
    k_agg<<<(N_NODES * 32 + 255) / 256, 256>>>(bufB, meanB);
    k_gemm<<<(N_NODES + 63) / 64, 256>>>(meanB, bufB, W3l, W3r, b3, bufA);

    // pool + classifier
    k_pool<<<(N_NODES + 255) / 256, 128>>>(bufA, batch);
    k_final<<<1, 64>>>(Wfc, bfc, out);
}

// round 2
// speedup vs baseline: 1.1437x; 1.1437x over previous
#include <cuda_runtime.h>
#include <cuda_bf16.h>

#define N_NODES  100000
#define N_EDGES  1600000
#define HID      128
#define N_GRAPHS 64
#define N_CLASSES 10
#define PADROWS  128

// ---------------- scratch (device globals; no allocation allowed) ----------------
__device__ float g_bufA[(N_NODES + PADROWS) * HID];
__device__ float g_bufB[(N_NODES + PADROWS) * HID];
__device__ float g_mean[(N_NODES + PADROWS) * HID];
__device__ float g_meanx[N_NODES];
__device__ int   g_cnt[N_NODES];
__device__ int   g_off[N_NODES + 1];
__device__ int   g_cur[N_NODES];
__device__ int   g_eidx[N_EDGES];
__device__ float g_pool[N_GRAPHS * HID];
__device__ int   g_pcnt[N_GRAPHS];
// packed transposed bf16 weights: [layer][n=128][kpair=128] (K=256 = Wl || Wr)
__device__ unsigned g_Wph[2 * 128 * 128];
__device__ unsigned g_Wpl[2 * 128 * 128];

// ---------------- helpers ----------------
__device__ __forceinline__ void split_bf16(float v, unsigned short& hi, unsigned short& lo) {
    __nv_bfloat16 h = __float2bfloat16(v);
    float hf = __bfloat162float(h);
    __nv_bfloat16 l = __float2bfloat16(v - hf);
    hi = __bfloat16_as_ushort(h);
    lo = __bfloat16_as_ushort(l);
}

__device__ __forceinline__ void mma16816(float* c, const unsigned* a, const unsigned* b) {
    asm volatile(
        "mma.sync.aligned.m16n8k16.row.col.f32.bf16.bf16.f32 "
        "{%0,%1,%2,%3},{%4,%5,%6,%7},{%8,%9},{%0,%1,%2,%3};\n"
        : "+f"(c[0]), "+f"(c[1]), "+f"(c[2]), "+f"(c[3])
        : "r"(a[0]), "r"(a[1]), "r"(a[2]), "r"(a[3]), "r"(b[0]), "r"(b[1]));
}

// ---------------- zero counters / pool ----------------
__global__ void k_zero() {
    int i = blockIdx.x * blockDim.x + threadIdx.x;
    if (i < N_NODES) g_cnt[i] = 0;
    if (i < N_GRAPHS * HID) g_pool[i] = 0.f;
    if (i < N_GRAPHS) g_pcnt[i] = 0;
}

// ---------------- degree histogram ----------------
__global__ void k_hist(const int* __restrict__ dst) {
    int e = blockIdx.x * blockDim.x + threadIdx.x;
    if (e < N_EDGES) atomicAdd(&g_cnt[dst[e]], 1);
}

// ---------------- single-block exclusive scan ----------------
__global__ void k_scan() {
    __shared__ int warpsum[32];
    __shared__ int carry_s;
    const int t = threadIdx.x, lane = t & 31, wid = t >> 5;
    if (t == 0) carry_s = 0;
    __syncthreads();
    for (int base = 0; base < N_NODES; base += 1024) {
        int i = base + t;
        int v = (i < N_NODES) ? g_cnt[i] : 0;
        int x = v;
        #pragma unroll
        for (int o = 1; o < 32; o <<= 1) {
            int y = __shfl_up_sync(0xffffffff, x, o);
            if (lane >= o) x += y;
        }
        if (lane == 31) warpsum[wid] = x;
        __syncthreads();
        if (wid == 0) {
            int w = warpsum[lane];
            int xs = w;
            #pragma unroll
            for (int o = 1; o < 32; o <<= 1) {
                int y = __shfl_up_sync(0xffffffff, xs, o);
                if (lane >= o) xs += y;
            }
            warpsum[lane] = xs - w;
        }
        __syncthreads();
        int excl = carry_s + warpsum[wid] + x - v;
        if (i < N_NODES) { g_off[i] = excl; g_cur[i] = excl; }
        __syncthreads();
        if (t == 1023) carry_s += warpsum[31] + x;
        __syncthreads();
    }
    if (t == 0) g_off[N_NODES] = carry_s;
}

// ---------------- scatter edges into CSR slots ----------------
__global__ void k_scatter(const int* __restrict__ src, const int* __restrict__ dst) {
    int e = blockIdx.x * blockDim.x + threadIdx.x;
    if (e < N_EDGES) {
        int pos = atomicAdd(&g_cur[dst[e]], 1);
        g_eidx[pos] = src[e];
    }
}

// ---------------- weight convert: fp32 [k][n] -> packed bf16 hi/lo [n][kpair] --
__global__ void k_convW(const float* __restrict__ W2l, const float* __restrict__ W2r,
                        const float* __restrict__ W3l, const float* __restrict__ W3r) {
    int idx = blockIdx.x * blockDim.x + threadIdx.x;   // 2*128*128
    if (idx >= 2 * 128 * 128) return;
    int layer = idx >> 14;
    int rem = idx & 16383;
    int n = rem >> 7;
    int kp = rem & 127;
    const float* W = (kp < 64) ? (layer ? W3l : W2l) : (layer ? W3r : W2r);
    int k = (kp < 64) ? (2 * kp) : (2 * kp - 128);
    float v0 = W[k * HID + n];
    float v1 = W[(k + 1) * HID + n];
    unsigned short h0, l0, h1, l1;
    split_bf16(v0, h0, l0);
    split_bf16(v1, h1, l1);
    g_Wph[idx] = (unsigned)h0 | ((unsigned)h1 << 16);
    g_Wpl[idx] = (unsigned)l0 | ((unsigned)l1 << 16);
}

// ---------------- layer-1 scalar aggregation ----------------
__global__ void k_aggx(const float* __restrict__ x) {
    int i = blockIdx.x * blockDim.x + threadIdx.x;
    if (i >= N_NODES) return;
    int b = g_off[i], e = g_off[i + 1];
    float s = 0.f;
    for (int j = b; j < e; j++) s += __ldg(&x[g_eidx[j]]);
    g_meanx[i] = s / (float)max(e - b, 1);
}

// ---------------- layer 1 ----------------
__global__ void k_layer1(const float* __restrict__ x,
                         const float* __restrict__ W1l,
                         const float* __restrict__ W1r,
                         const float* __restrict__ b1,
                         float* __restrict__ out) {
    int idx = blockIdx.x * blockDim.x + threadIdx.x;
    if (idx >= N_NODES * HID) return;
    int i = idx >> 7;
    int f = idx & 127;
    float v = g_meanx[i] * __ldg(&W1l[f]) + __ldg(&x[i]) * __ldg(&W1r[f]) + __ldg(&b1[f]);
    out[idx] = fmaxf(v, 0.f);
}

// ---------------- 128-dim mean aggregation: warp per node ----------------
__global__ void k_agg(const float* __restrict__ h, float* __restrict__ outMean) {
    int node = (blockIdx.x * blockDim.x + threadIdx.x) >> 5;
    int lane = threadIdx.x & 31;
    if (node >= N_NODES) return;
    int beg = g_off[node], end = g_off[node + 1];
    float ax = 0.f, ay = 0.f, az = 0.f, aw = 0.f;
    const float4* hv = (const float4*)h;
    for (int e = beg; e < end; e++) {
        int s = __ldg(&g_eidx[e]);
        float4 v = __ldg(&hv[s * 32 + lane]);
        ax += v.x; ay += v.y; az += v.z; aw += v.w;
    }
    float inv = 1.f / (float)max(end - beg, 1);
    float4 o = make_float4(ax * inv, ay * inv, az * inv, aw * inv);
    ((float4*)outMean)[node * 32 + lane] = o;
}

// ---------------- tensor-core SAGE GEMM: out = relu([mean|h] @ [Wl;Wr] + b) ----
// M=100000(+pad), N=128, K=256.  BM=128, BN=128, BK=32.
// 8 warps in 2x4 grid; warp tile 64x32 = 4x4 m16n8 tiles.
// 3x bf16-split MMA (hi*hi + hi*lo + lo*hi) => ~fp32 precision.
#define SSTR 20
__global__ __launch_bounds__(256, 1) void k_gemm_tc(
    const float* __restrict__ Am, const float* __restrict__ Ah,
    const unsigned* __restrict__ Wph, const unsigned* __restrict__ Wpl,
    const float* __restrict__ bias, float* __restrict__ out)
{
    __shared__ unsigned As_h[128][SSTR], As_l[128][SSTR];
    __shared__ unsigned Ws_h[128][SSTR], Ws_l[128][SSTR];
    const int t = threadIdx.x;
    const int lane = t & 31, w = t >> 5;
    const int wm = w >> 2, wn = w & 3;          // 2 x 4 warps
    const int g = lane >> 2, tid4 = lane & 3;
    const int m0 = blockIdx.x * 128;

    float acc[4][4][4];
    #pragma unroll
    for (int a = 0; a < 4; a++)
        #pragma unroll
        for (int b = 0; b < 4; b++)
            #pragma unroll
            for (int c = 0; c < 4; c++) acc[a][b][c] = 0.f;

    for (int kb = 0; kb < 256; kb += 32) {
        const float* Ab = (kb < 128) ? Am : Ah;
        const int koff = kb & 127;
        // A tile fill: 128 rows x 16 kpairs (convert fp32 -> bf16 hi/lo)
        #pragma unroll
        for (int it = 0; it < 8; it++) {
            int idx = t + it * 256;             // 0..2047
            int r = idx >> 4, kp = idx & 15;
            float2 v = *(const float2*)&Ab[(m0 + r) * HID + koff + kp * 2];
            unsigned short h0, l0, h1, l1;
            split_bf16(v.x, h0, l0);
            split_bf16(v.y, h1, l1);
            As_h[r][kp] = (unsigned)h0 | ((unsigned)h1 << 16);
            As_l[r][kp] = (unsigned)l0 | ((unsigned)l1 << 16);
        }
        // W tile fill: straight copy from packed global
        const int kb2 = kb >> 1;                // kpair offset
        #pragma unroll
        for (int it = 0; it < 8; it++) {
            int idx = t + it * 256;
            int n = idx >> 4, kp = idx & 15;
            Ws_h[n][kp] = Wph[n * 128 + kb2 + kp];
            Ws_l[n][kp] = Wpl[n * 128 + kb2 + kp];
        }
        __syncthreads();
        #pragma unroll
        for (int ks = 0; ks < 2; ks++) {
            const int kp0 = ks * 8 + tid4;
            unsigned ah[4][4], al[4][4], bh[4][2], bl[4][2];
            #pragma unroll
            for (int mt = 0; mt < 4; mt++) {
                int r = wm * 64 + mt * 16 + g;
                ah[mt][0] = As_h[r][kp0];     ah[mt][1] = As_h[r + 8][kp0];
                ah[mt][2] = As_h[r][kp0 + 4]; ah[mt][3] = As_h[r + 8][kp0 + 4];
                al[mt][0] = As_l[r][kp0];     al[mt][1] = As_l[r + 8][kp0];
                al[mt][2] = As_l[r][kp0 + 4]; al[mt][3] = As_l[r + 8][kp0 + 4];
            }
            #pragma unroll
            for (int nt = 0; nt < 4; nt++) {
                int n = wn * 32 + nt * 8 + g;
                bh[nt][0] = Ws_h[n][kp0]; bh[nt][1] = Ws_h[n][kp0 + 4];
                bl[nt][0] = Ws_l[n][kp0]; bl[nt][1] = Ws_l[n][kp0 + 4];
            }
            #pragma unroll
            for (int mt = 0; mt < 4; mt++)
                #pragma unroll
                for (int nt = 0; nt < 4; nt++) {
                    mma16816(acc[mt][nt], ah[mt], bh[nt]);
                    mma16816(acc[mt][nt], ah[mt], bl[nt]);
                    mma16816(acc[mt][nt], al[mt], bh[nt]);
                }
        }
        __syncthreads();
    }
    // epilogue: bias + relu, float2 stores (pad rows absorb tail)
    #pragma unroll
    for (int nt = 0; nt < 4; nt++) {
        int col = wn * 32 + nt * 8 + tid4 * 2;
        float b0 = __ldg(&bias[col]), b1 = __ldg(&bias[col + 1]);
        #pragma unroll
        for (int mt = 0; mt < 4; mt++) {
            int row = m0 + wm * 64 + mt * 16 + g;
            float2 o0, o1;
            o0.x = fmaxf(acc[mt][nt][0] + b0, 0.f);
            o0.y = fmaxf(acc[mt][nt][1] + b1, 0.f);
            o1.x = fmaxf(acc[mt][nt][2] + b0, 0.f);
            o1.y = fmaxf(acc[mt][nt][3] + b1, 0.f);
            *(float2*)&out[row * HID + col] = o0;
            *(float2*)&out[(row + 8) * HID + col] = o1;
        }
    }
}

// ---------------- global mean pool ----------------
__global__ void k_pool(const float* __restrict__ h, const int* __restrict__ batch) {
    const int f = threadIdx.x;
    const int start = blockIdx.x * 256;
    if (start >= N_NODES) return;
    const int end = min(start + 256, N_NODES);
    float sum = 0.f;
    int cnt = 0;
    int cur = __ldg(&batch[start]);
    for (int i = start; i < end; i++) {
        int gid = __ldg(&batch[i]);
        if (gid != cur) {
            atomicAdd(&g_pool[cur * HID + f], sum);
            if (f == 0) atomicAdd(&g_pcnt[cur], cnt);
            sum = 0.f; cnt = 0; cur = gid;
        }
        sum += h[i * HID + f];
        cnt++;
    }
    atomicAdd(&g_pool[cur * HID + f], sum);
    if (f == 0) atomicAdd(&g_pcnt[cur], cnt);
}

// ---------------- final FC + log_softmax ----------------
__global__ void k_final(const float* __restrict__ Wfc,
                        const float* __restrict__ bfc,
                        float* __restrict__ out) {
    int g = threadIdx.x;
    if (g >= N_GRAPHS) return;
    float inv = 1.f / fmaxf((float)g_pcnt[g], 1.f);
    float logits[N_CLASSES];
    #pragma unroll
    for (int c = 0; c < N_CLASSES; c++) logits[c] = __ldg(&bfc[c]);
    for (int k = 0; k < HID; k++) {
        float p = g_pool[g * HID + k] * inv;
        #pragma unroll
        for (int c = 0; c < N_CLASSES; c++)
            logits[c] += p * __ldg(&Wfc[k * N_CLASSES + c]);
    }
    float mx = logits[0];
    #pragma unroll
    for (int c = 1; c < N_CLASSES; c++) mx = fmaxf(mx, logits[c]);
    float s = 0.f;
    #pragma unroll
    for (int c = 0; c < N_CLASSES; c++) s += expf(logits[c] - mx);
    float lse = logf(s) + mx;
    #pragma unroll
    for (int c = 0; c < N_CLASSES; c++) out[g * N_CLASSES + c] = logits[c] - lse;
}

// ---------------- launch ----------------
extern "C" void kernel_launch(void* const* d_in, const int* in_sizes, int n_in,
                              void* d_out, int out_size) {
    const float* x     = (const float*)d_in[0];
    const int*   eidx  = (const int*)d_in[1];
    const int*   batch = (const int*)d_in[2];
    const float* W1l = (const float*)d_in[3];
    const float* W1r = (const float*)d_in[4];
    const float* b1  = (const float*)d_in[5];
    const float* W2l = (const float*)d_in[6];
    const float* W2r = (const float*)d_in[7];
    const float* b2  = (const float*)d_in[8];
    const float* W3l = (const float*)d_in[9];
    const float* W3r = (const float*)d_in[10];
    const float* b3  = (const float*)d_in[11];
    const float* Wfc = (const float*)d_in[12];
    const float* bfc = (const float*)d_in[13];
    float* out = (float*)d_out;

    const int* src = eidx;
    const int* dst = eidx + N_EDGES;

    float *bufA, *bufB, *meanB;
    unsigned *wph, *wpl;
    cudaGetSymbolAddress((void**)&bufA,  g_bufA);
    cudaGetSymbolAddress((void**)&bufB,  g_bufB);
    cudaGetSymbolAddress((void**)&meanB, g_mean);
    cudaGetSymbolAddress((void**)&wph,   g_Wph);
    cudaGetSymbolAddress((void**)&wpl,   g_Wpl);

    // CSR build + weight packing
    k_zero<<<(N_NODES + 255) / 256, 256>>>();
    k_hist<<<(N_EDGES + 255) / 256, 256>>>(dst);
    k_convW<<<(2 * 128 * 128 + 255) / 256, 256>>>(W2l, W2r, W3l, W3r);
    k_scan<<<1, 1024>>>();
    k_scatter<<<(N_EDGES + 255) / 256, 256>>>(src, dst);

    // layer 1 (scalar features)
    k_aggx<<<(N_NODES + 255) / 256, 256>>>(x);
    k_layer1<<<(N_NODES * HID + 255) / 256, 256>>>(x, W1l, W1r, b1, bufA);

    // layer 2
    k_agg<<<(N_NODES * 32 + 255) / 256, 256>>>(bufA, meanB);
    k_gemm_tc<<<(N_NODES + 127) / 128, 256>>>(meanB, bufA, wph, wpl, b2, bufB);

    // layer 3
    k_agg<<<(N_NODES * 32 + 255) / 256, 256>>>(bufB, meanB);
    k_gemm_tc<<<(N_NODES + 127) / 128, 256>>>(meanB, bufB, wph + 128 * 128, wpl + 128 * 128, b3, bufA);

    // pool + classifier
    k_pool<<<(N_NODES + 255) / 256, 128>>>(bufA, batch);
    k_final<<<1, 64>>>(Wfc, bfc, out);
}

// round 3
// speedup vs baseline: 1.2969x; 1.1339x over previous
#include <cuda_runtime.h>
#include <cuda_bf16.h>

#define N_NODES  100000
#define N_EDGES  1600000
#define HID      128
#define N_GRAPHS 64
#define N_CLASSES 10
#define PADROWS  128
#define SCAN_BLOCKS 98   // ceil(100000/1024)

// ---------------- scratch (device globals; no allocation allowed) ----------------
__device__ float g_bufA[(N_NODES + PADROWS) * HID];
__device__ float g_bufB[(N_NODES + PADROWS) * HID];
__device__ float g_mean[(N_NODES + PADROWS) * HID];
__device__ float g_meanx[N_NODES];
__device__ int   g_cnt[N_NODES];
__device__ int   g_off[N_NODES + 1];
__device__ int   g_cur[N_NODES];
__device__ int   g_eidx[N_EDGES];
__device__ float g_pool[N_GRAPHS * HID];
__device__ int   g_pcnt[N_GRAPHS];
__device__ int   g_bsum[128];
__device__ int   g_bpre[128];
// packed transposed bf16 weights: [layer][n=128][kpair=128] (K=256 = Wl || Wr)
__device__ unsigned g_Wph[2 * 128 * 128];
__device__ unsigned g_Wpl[2 * 128 * 128];

// ---------------- helpers ----------------
__device__ __forceinline__ void split_bf16(float v, unsigned short& hi, unsigned short& lo) {
    __nv_bfloat16 h = __float2bfloat16(v);
    float hf = __bfloat162float(h);
    __nv_bfloat16 l = __float2bfloat16(v - hf);
    hi = __bfloat16_as_ushort(h);
    lo = __bfloat16_as_ushort(l);
}

__device__ __forceinline__ void mma16816(float* c, const unsigned* a, const unsigned* b) {
    asm volatile(
        "mma.sync.aligned.m16n8k16.row.col.f32.bf16.bf16.f32 "
        "{%0,%1,%2,%3},{%4,%5,%6,%7},{%8,%9},{%0,%1,%2,%3};\n"
        : "+f"(c[0]), "+f"(c[1]), "+f"(c[2]), "+f"(c[3])
        : "r"(a[0]), "r"(a[1]), "r"(a[2]), "r"(a[3]), "r"(b[0]), "r"(b[1]));
}

// ---------------- zero counters / pool ----------------
__global__ void k_zero() {
    int i = blockIdx.x * blockDim.x + threadIdx.x;
    if (i < N_NODES) g_cnt[i] = 0;
    if (i < N_GRAPHS * HID) g_pool[i] = 0.f;
    if (i < N_GRAPHS) g_pcnt[i] = 0;
}

// ---------------- degree histogram ----------------
__global__ void k_hist(const int* __restrict__ dst) {
    int e = blockIdx.x * blockDim.x + threadIdx.x;
    if (e < N_EDGES) atomicAdd(&g_cnt[dst[e]], 1);
}

// ---------------- multi-block scan, phase 1: block-local exclusive scan ------
__global__ void k_scan1() {
    __shared__ int warpsum[32];
    const int t = threadIdx.x, lane = t & 31, wid = t >> 5;
    int i = blockIdx.x * 1024 + t;
    int v = (i < N_NODES) ? g_cnt[i] : 0;
    int x = v;
    #pragma unroll
    for (int o = 1; o < 32; o <<= 1) {
        int y = __shfl_up_sync(0xffffffff, x, o);
        if (lane >= o) x += y;
    }
    if (lane == 31) warpsum[wid] = x;          // inclusive warp total
    __syncthreads();
    if (wid == 0) {
        int w = warpsum[lane];
        int xs = w;
        #pragma unroll
        for (int o = 1; o < 32; o <<= 1) {
            int y = __shfl_up_sync(0xffffffff, xs, o);
            if (lane >= o) xs += y;
        }
        warpsum[lane] = xs - w;                // exclusive warp prefix
    }
    __syncthreads();
    int excl = warpsum[wid] + x - v;           // block-local exclusive
    if (i < N_NODES) g_off[i] = excl;
    if (t == 1023) g_bsum[blockIdx.x] = excl + v;   // block total
}

// ---------------- phase 2: scan block totals (1 block, 128 threads) ----------
__global__ void k_scan2() {
    __shared__ int wsum[4];
    const int t = threadIdx.x, lane = t & 31, wid = t >> 5;
    int v = (t < SCAN_BLOCKS) ? g_bsum[t] : 0;
    int x = v;
    #pragma unroll
    for (int o = 1; o < 32; o <<= 1) {
        int y = __shfl_up_sync(0xffffffff, x, o);
        if (lane >= o) x += y;
    }
    if (lane == 31) wsum[wid] = x;
    __syncthreads();
    int pre = 0;
    #pragma unroll
    for (int wdx = 0; wdx < 4; wdx++) if (wdx < wid) pre += wsum[wdx];
    int excl = pre + x - v;
    if (t < SCAN_BLOCKS) g_bpre[t] = excl;
    if (t == SCAN_BLOCKS - 1) g_off[N_NODES] = excl + v;
}

// ---------------- phase 3: add block prefixes ----------------
__global__ void k_scan3() {
    int i = blockIdx.x * 1024 + threadIdx.x;
    if (i < N_NODES) {
        int o = g_off[i] + g_bpre[blockIdx.x];
        g_off[i] = o;
        g_cur[i] = o;
    }
}

// ---------------- scatter edges into CSR slots ----------------
__global__ void k_scatter(const int* __restrict__ src, const int* __restrict__ dst) {
    int e = blockIdx.x * blockDim.x + threadIdx.x;
    if (e < N_EDGES) {
        int pos = atomicAdd(&g_cur[dst[e]], 1);
        g_eidx[pos] = src[e];
    }
}

// ---------------- weight convert: fp32 [k][n] -> packed bf16 hi/lo [n][kpair] --
__global__ void k_convW(const float* __restrict__ W2l, const float* __restrict__ W2r,
                        const float* __restrict__ W3l, const float* __restrict__ W3r) {
    int idx = blockIdx.x * blockDim.x + threadIdx.x;   // 2*128*128
    if (idx >= 2 * 128 * 128) return;
    int layer = idx >> 14;
    int rem = idx & 16383;
    int n = rem >> 7;
    int kp = rem & 127;
    const float* W = (kp < 64) ? (layer ? W3l : W2l) : (layer ? W3r : W2r);
    int k = (kp < 64) ? (2 * kp) : (2 * kp - 128);
    float v0 = W[k * HID + n];
    float v1 = W[(k + 1) * HID + n];
    unsigned short h0, l0, h1, l1;
    split_bf16(v0, h0, l0);
    split_bf16(v1, h1, l1);
    g_Wph[idx] = (unsigned)h0 | ((unsigned)h1 << 16);
    g_Wpl[idx] = (unsigned)l0 | ((unsigned)l1 << 16);
}

// ---------------- layer-1 scalar aggregation ----------------
__global__ void k_aggx(const float* __restrict__ x) {
    int i = blockIdx.x * blockDim.x + threadIdx.x;
    if (i >= N_NODES) return;
    int b = g_off[i], e = g_off[i + 1];
    float s = 0.f;
    for (int j = b; j < e; j++) s += __ldg(&x[g_eidx[j]]);
    g_meanx[i] = s / (float)max(e - b, 1);
}

// ---------------- layer 1 ----------------
__global__ void k_layer1(const float* __restrict__ x,
                         const float* __restrict__ W1l,
                         const float* __restrict__ W1r,
                         const float* __restrict__ b1,
                         float* __restrict__ out) {
    int idx = blockIdx.x * blockDim.x + threadIdx.x;
    if (idx >= N_NODES * HID) return;
    int i = idx >> 7;
    int f = idx & 127;
    float v = g_meanx[i] * __ldg(&W1l[f]) + __ldg(&x[i]) * __ldg(&W1r[f]) + __ldg(&b1[f]);
    out[idx] = fmaxf(v, 0.f);
}

// ---------------- 128-dim mean aggregation: warp per node ----------------
__global__ void k_agg(const float* __restrict__ h, float* __restrict__ outMean) {
    int node = (blockIdx.x * blockDim.x + threadIdx.x) >> 5;
    int lane = threadIdx.x & 31;
    if (node >= N_NODES) return;
    int beg = g_off[node], end = g_off[node + 1];
    float ax = 0.f, ay = 0.f, az = 0.f, aw = 0.f;
    const float4* hv = (const float4*)h;
    for (int e = beg; e < end; e++) {
        int s = __ldg(&g_eidx[e]);
        float4 v = __ldg(&hv[s * 32 + lane]);
        ax += v.x; ay += v.y; az += v.z; aw += v.w;
    }
    float inv = 1.f / (float)max(end - beg, 1);
    float4 o = make_float4(ax * inv, ay * inv, az * inv, aw * inv);
    ((float4*)outMean)[node * 32 + lane] = o;
}

// ---------------- tensor-core SAGE GEMM: out = relu([mean|h] @ [Wl;Wr] + b) ----
// M=100000(+pad), N=128, K=256.  BM=128, BN=128, BK=32.
// 8 warps in 2x4 grid; warp tile 64x32 = 4x4 m16n8 tiles.
// 3x bf16-split MMA (hi*hi + hi*lo + lo*hi) => ~fp32 precision.
#define SSTR 20
__global__ __launch_bounds__(256, 1) void k_gemm_tc(
    const float* __restrict__ Am, const float* __restrict__ Ah,
    const unsigned* __restrict__ Wph, const unsigned* __restrict__ Wpl,
    const float* __restrict__ bias, float* __restrict__ out)
{
    __shared__ unsigned As_h[128][SSTR], As_l[128][SSTR];
    __shared__ unsigned Ws_h[128][SSTR], Ws_l[128][SSTR];
    const int t = threadIdx.x;
    const int lane = t & 31, w = t >> 5;
    const int wm = w >> 2, wn = w & 3;          // 2 x 4 warps
    const int g = lane >> 2, tid4 = lane & 3;
    const int m0 = blockIdx.x * 128;

    float acc[4][4][4];
    #pragma unroll
    for (int a = 0; a < 4; a++)
        #pragma unroll
        for (int b = 0; b < 4; b++)
            #pragma unroll
            for (int c = 0; c < 4; c++) acc[a][b][c] = 0.f;

    for (int kb = 0; kb < 256; kb += 32) {
        const float* Ab = (kb < 128) ? Am : Ah;
        const int koff = kb & 127;
        // A tile fill: 128 rows x 16 kpairs (convert fp32 -> bf16 hi/lo)
        #pragma unroll
        for (int it = 0; it < 8; it++) {
            int idx = t + it * 256;             // 0..2047
            int r = idx >> 4, kp = idx & 15;
            float2 v = *(const float2*)&Ab[(m0 + r) * HID + koff + kp * 2];
            unsigned short h0, l0, h1, l1;
            split_bf16(v.x, h0, l0);
            split_bf16(v.y, h1, l1);
            As_h[r][kp] = (unsigned)h0 | ((unsigned)h1 << 16);
            As_l[r][kp] = (unsigned)l0 | ((unsigned)l1 << 16);
        }
        // W tile fill: straight copy from packed global
        const int kb2 = kb >> 1;                // kpair offset
        #pragma unroll
        for (int it = 0; it < 8; it++) {
            int idx = t + it * 256;
            int n = idx >> 4, kp = idx & 15;
            Ws_h[n][kp] = Wph[n * 128 + kb2 + kp];
            Ws_l[n][kp] = Wpl[n * 128 + kb2 + kp];
        }
        __syncthreads();
        #pragma unroll
        for (int ks = 0; ks < 2; ks++) {
            const int kp0 = ks * 8 + tid4;
            unsigned ah[4][4], al[4][4], bh[4][2], bl[4][2];
            #pragma unroll
            for (int mt = 0; mt < 4; mt++) {
                int r = wm * 64 + mt * 16 + g;
                ah[mt][0] = As_h[r][kp0];     ah[mt][1] = As_h[r + 8][kp0];
                ah[mt][2] = As_h[r][kp0 + 4]; ah[mt][3] = As_h[r + 8][kp0 + 4];
                al[mt][0] = As_l[r][kp0];     al[mt][1] = As_l[r + 8][kp0];
                al[mt][2] = As_l[r][kp0 + 4]; al[mt][3] = As_l[r + 8][kp0 + 4];
            }
            #pragma unroll
            for (int nt = 0; nt < 4; nt++) {
                int n = wn * 32 + nt * 8 + g;
                bh[nt][0] = Ws_h[n][kp0]; bh[nt][1] = Ws_h[n][kp0 + 4];
                bl[nt][0] = Ws_l[n][kp0]; bl[nt][1] = Ws_l[n][kp0 + 4];
            }
            #pragma unroll
            for (int mt = 0; mt < 4; mt++)
                #pragma unroll
                for (int nt = 0; nt < 4; nt++) {
                    mma16816(acc[mt][nt], ah[mt], bh[nt]);
                    mma16816(acc[mt][nt], ah[mt], bl[nt]);
                    mma16816(acc[mt][nt], al[mt], bh[nt]);
                }
        }
        __syncthreads();
    }
    // epilogue: bias + relu, float2 stores (pad rows absorb tail)
    #pragma unroll
    for (int nt = 0; nt < 4; nt++) {
        int col = wn * 32 + nt * 8 + tid4 * 2;
        float b0 = __ldg(&bias[col]), b1 = __ldg(&bias[col + 1]);
        #pragma unroll
        for (int mt = 0; mt < 4; mt++) {
            int row = m0 + wm * 64 + mt * 16 + g;
            float2 o0, o1;
            o0.x = fmaxf(acc[mt][nt][0] + b0, 0.f);
            o0.y = fmaxf(acc[mt][nt][1] + b1, 0.f);
            o1.x = fmaxf(acc[mt][nt][2] + b0, 0.f);
            o1.y = fmaxf(acc[mt][nt][3] + b1, 0.f);
            *(float2*)&out[row * HID + col] = o0;
            *(float2*)&out[(row + 8) * HID + col] = o1;
        }
    }
}

// ---------------- global mean pool ----------------
__global__ void k_pool(const float* __restrict__ h, const int* __restrict__ batch) {
    const int f = threadIdx.x;
    const int start = blockIdx.x * 256;
    if (start >= N_NODES) return;
    const int end = min(start + 256, N_NODES);
    float sum = 0.f;
    int cnt = 0;
    int cur = __ldg(&batch[start]);
    for (int i = start; i < end; i++) {
        int gid = __ldg(&batch[i]);
        if (gid != cur) {
            atomicAdd(&g_pool[cur * HID + f], sum);
            if (f == 0) atomicAdd(&g_pcnt[cur], cnt);
            sum = 0.f; cnt = 0; cur = gid;
        }
        sum += h[i * HID + f];
        cnt++;
    }
    atomicAdd(&g_pool[cur * HID + f], sum);
    if (f == 0) atomicAdd(&g_pcnt[cur], cnt);
}

// ---------------- final FC + log_softmax ----------------
__global__ void k_final(const float* __restrict__ Wfc,
                        const float* __restrict__ bfc,
                        float* __restrict__ out) {
    int g = threadIdx.x;
    if (g >= N_GRAPHS) return;
    float inv = 1.f / fmaxf((float)g_pcnt[g], 1.f);
    float logits[N_CLASSES];
    #pragma unroll
    for (int c = 0; c < N_CLASSES; c++) logits[c] = __ldg(&bfc[c]);
    for (int k = 0; k < HID; k++) {
        float p = g_pool[g * HID + k] * inv;
        #pragma unroll
        for (int c = 0; c < N_CLASSES; c++)
            logits[c] += p * __ldg(&Wfc[k * N_CLASSES + c]);
    }
    float mx = logits[0];
    #pragma unroll
    for (int c = 1; c < N_CLASSES; c++) mx = fmaxf(mx, logits[c]);
    float s = 0.f;
    #pragma unroll
    for (int c = 0; c < N_CLASSES; c++) s += expf(logits[c] - mx);
    float lse = logf(s) + mx;
    #pragma unroll
    for (int c = 0; c < N_CLASSES; c++) out[g * N_CLASSES + c] = logits[c] - lse;
}

// ---------------- launch ----------------
extern "C" void kernel_launch(void* const* d_in, const int* in_sizes, int n_in,
                              void* d_out, int out_size) {
    const float* x     = (const float*)d_in[0];
    const int*   eidx  = (const int*)d_in[1];
    const int*   batch = (const int*)d_in[2];
    const float* W1l = (const float*)d_in[3];
    const float* W1r = (const float*)d_in[4];
    const float* b1  = (const float*)d_in[5];
    const float* W2l = (const float*)d_in[6];
    const float* W2r = (const float*)d_in[7];
    const float* b2  = (const float*)d_in[8];
    const float* W3l = (const float*)d_in[9];
    const float* W3r = (const float*)d_in[10];
    const float* b3  = (const float*)d_in[11];
    const float* Wfc = (const float*)d_in[12];
    const float* bfc = (const float*)d_in[13];
    float* out = (float*)d_out;

    const int* src = eidx;
    const int* dst = eidx + N_EDGES;

    float *bufA, *bufB, *meanB;
    unsigned *wph, *wpl;
    cudaGetSymbolAddress((void**)&bufA,  g_bufA);
    cudaGetSymbolAddress((void**)&bufB,  g_bufB);
    cudaGetSymbolAddress((void**)&meanB, g_mean);
    cudaGetSymbolAddress((void**)&wph,   g_Wph);
    cudaGetSymbolAddress((void**)&wpl,   g_Wpl);

    // CSR build + weight packing
    k_zero<<<(N_NODES + 255) / 256, 256>>>();
    k_hist<<<(N_EDGES + 255) / 256, 256>>>(dst);
    k_convW<<<(2 * 128 * 128 + 255) / 256, 256>>>(W2l, W2r, W3l, W3r);
    k_scan1<<<SCAN_BLOCKS, 1024>>>();
    k_scan2<<<1, 128>>>();
    k_scan3<<<SCAN_BLOCKS, 1024>>>();
    k_scatter<<<(N_EDGES + 255) / 256, 256>>>(src, dst);

    // layer 1 (scalar features)
    k_aggx<<<(N_NODES + 255) / 256, 256>>>(x);
    k_layer1<<<(N_NODES * HID + 255) / 256, 256>>>(x, W1l, W1r, b1, bufA);

    // layer 2
    k_agg<<<(N_NODES * 32 + 255) / 256, 256>>>(bufA, meanB);
    k_gemm_tc<<<(N_NODES + 127) / 128, 256>>>(meanB, bufA, wph, wpl, b2, bufB);

    // layer 3
    k_agg<<<(N_NODES * 32 + 255) / 256, 256>>>(bufB, meanB);
    k_gemm_tc<<<(N_NODES + 127) / 128, 256>>>(meanB, bufB, wph + 128 * 128, wpl + 128 * 128, b3, bufA);

    // pool + classifier
    k_pool<<<(N_NODES + 255) / 256, 128>>>(bufA, batch);
    k_final<<<1, 64>>>(Wfc, bfc, out);
}